// round 17
// baseline (speedup 1.0000x reference)
#include <cuda_runtime.h>
#include <cstdint>

#define BB   32
#define TT   336
#define NH   100
#define NM   150
#define FH   8
#define FM   16
#define HG   64
#define HL   64
#define FUT  24
#define TCB  48          // timesteps per producer/gnn chunk
#define TF   16          // timesteps per flag granule
#define NCK  (TT / TF)   // 21 flag granules
#define NPB  (TT / TCB)  // 7 chunks
#define GPC  96          // gnn blocks per chunk
#define GRP  (GPC + NH)  // 196

typedef unsigned long long u64;

#define FMA2(d, a, b) \
    asm("fma.rn.f32x2 %0, %1, %2, %0;" : "+l"(d) : "l"(a), "l"(b))
#define PACK2(d, v) \
    asm("mov.b64 %0, {%1, %1};" : "=l"(d) : "r"(__float_as_uint(v)))
#define UNPACK2(lo, hi, x) \
    asm("mov.b64 {%0, %1}, %2;" : "=f"(lo), "=f"(hi) : "l"(x))

// GNN output x: [n][t][b][hg]
__device__ float g_x[(size_t)NH * TT * BB * HG];
// Precomputed x-gates (+bias): [n][t][b][256]
__device__ float g_gates[(size_t)NH * TT * BB * 256];
// xgemm->lstm readiness flags
__device__ int d_flag[NH * NCK];
// gnn->xgemm chunk counters (target GPC)
__device__ int d_cnt[NPB];

// CSR edge structure
__device__ int d_off_h[NH], d_deg_h[NH], d_src_h[512];
__device__ int d_off_m[NH], d_deg_m[NH], d_src_m[1024];

// ---------------------------------------------------------------------------
// Kernel A0: build CSR; zero handshake state.
// ---------------------------------------------------------------------------
__global__ void __launch_bounds__(256) csr_kernel(
    const int* __restrict__ eh, const int* __restrict__ em, int Eh, int Em)
{
    __shared__ int s_src[1024], s_tgt[1024];
    const int tid = threadIdx.x;

    for (int i = tid; i < NH * NCK; i += 256) d_flag[i] = 0;
    if (tid < NPB) d_cnt[tid] = 0;

    for (int i = tid; i < Eh; i += 256) { s_src[i] = eh[i]; s_tgt[i] = eh[Eh + i]; }
    __syncthreads();
    if (tid < NH) {
        int start = 0;
        for (int e = 0; e < Eh; e++) start += (s_tgt[e] < tid) ? 1 : 0;
        int p = start, cnt = 0;
        for (int e = 0; e < Eh; e++)
            if (s_tgt[e] == tid) { d_src_h[p++] = s_src[e]; cnt++; }
        d_off_h[tid] = start; d_deg_h[tid] = cnt;
    }
    __syncthreads();
    for (int i = tid; i < Em; i += 256) { s_src[i] = em[i]; s_tgt[i] = em[Em + i]; }
    __syncthreads();
    if (tid < NH) {
        int start = 0;
        for (int e = 0; e < Em; e++) start += (s_tgt[e] < tid) ? 1 : 0;
        int p = start, cnt = 0;
        for (int e = 0; e < Em; e++)
            if (s_tgt[e] == tid) { d_src_m[p++] = s_src[e]; cnt++; }
        d_off_m[tid] = start; d_deg_m[tid] = cnt;
    }
}

// ---------------------------------------------------------------------------
// FUSED pipeline kernel (schedule identical to R15/R16).
// ---------------------------------------------------------------------------
#define O_WHH 0
#define O_HL  16384
#define O_WL  (O_HL + 64*33)
#define O_BL  (O_WL + 24*64)
#define LS_FLOATS (O_BL + 32)
#define XG_SW 0
#define XG_SB 16384
#define XG_SX (16384 + 256)            // xdup [k][2b] stride 66: 4224
#define XG_FLOATS (XG_SX + 64*66)
#define G_WH  0
#define G_WR  512
#define G_WM  1024
#define G_SB  2048
#define G_INT 2112
#define G_XH  4048
#define G_XM  4848
#define G_AH  7248
#define G_AM  8048
#define FUSED_FLOATS (LS_FLOATS > XG_FLOATS ? LS_FLOATS : XG_FLOATS)
#define FUSED_BYTES  (FUSED_FLOATS * 4)

__device__ __forceinline__ float sigm(float x) {
    return 1.0f / (1.0f + __expf(-x));
}
__device__ __forceinline__ float tanh_fast(float x) {
    float xc = fminf(fmaxf(x, -15.f), 15.f);
    float e = __expf(2.0f * xc);
    return (e - 1.0f) / (e + 1.0f);
}
__device__ __forceinline__ void wait_flag(const int* f) {
    int v;
    for (;;) {
        asm volatile("ld.acquire.gpu.s32 %0, [%1];" : "=r"(v) : "l"(f) : "memory");
        if (v) break;
        __nanosleep(200);
    }
}
__device__ __forceinline__ void wait_cnt(const int* f, int target) {
    int v;
    for (;;) {
        asm volatile("ld.acquire.gpu.s32 %0, [%1];" : "=r"(v) : "l"(f) : "memory");
        if (v >= target) break;
        __nanosleep(200);
    }
}

__global__ void __launch_bounds__(256) fused_kernel(
    const float* __restrict__ xm_all, const float* __restrict__ xh_all,
    const float* __restrict__ Wrel_m, const float* __restrict__ brel_m,
    const float* __restrict__ Wroot_m,
    const float* __restrict__ Wrel_h, const float* __restrict__ brel_h,
    const float* __restrict__ Wroot_h,
    const float* __restrict__ W_ih, const float* __restrict__ W_hh,
    const float* __restrict__ b_ih, const float* __restrict__ b_hh,
    const float* __restrict__ W_lin, const float* __restrict__ b_lin,
    float* __restrict__ out)
{
    extern __shared__ float sm[];
    const int tid = threadIdx.x;

    // ---- role decode ----
    const int bx = blockIdx.x;
    int role, ci = 0, sub;
    if (bx < GPC)               { role = 0; ci = 0; sub = bx; }
    else if (bx < GPC + NH)     { role = 2;         sub = bx - GPC; }
    else if (bx < GPC + 2 * NH) { role = 1; ci = 0; sub = bx - GPC - NH; }
    else {
        int r = bx - (GPC + 2 * NH);
        ci = 1 + r / GRP;
        int w = r % GRP;
        if (w < GPC) { role = 0; sub = w; }
        else         { role = 1; sub = w - GPC; }
    }

    if (role == 0) {
        // =================== gnn producer: FFMA2 over unit pairs ============
        float* swh = sm + G_WH;
        float* swr = sm + G_WR;
        float* swm = sm + G_WM;
        float* sb  = sm + G_SB;
        int*   ip  = (int*)(sm + G_INT);
        int *soff_h = ip,        *sdeg_h = ip + 100,  *ssrc_h = ip + 200;
        int *soff_m = ip + 712,  *sdeg_m = ip + 812,  *ssrc_m = ip + 912;
        float* sxh = sm + G_XH;
        float* sxm = sm + G_XM;
        float* sah = sm + G_AH;
        float* sam = sm + G_AM;

        for (int i = tid; i < HG * FH; i += 256) {
            int j = i / FH, k = i % FH;
            swh[k * HG + j] = 0.5f * Wrel_h[i];
            swr[k * HG + j] = 0.5f * (Wroot_h[i] + Wroot_m[i]);
        }
        for (int i = tid; i < HG * FM; i += 256) {
            int j = i / FM, k = i % FM;
            swm[k * HG + j] = 0.5f * Wrel_m[i];
        }
        for (int i = tid; i < HG; i += 256)
            sb[i] = 0.5f * (brel_h[i] + brel_m[i]);
        for (int i = tid; i < NH; i += 256) {
            soff_h[i] = d_off_h[i]; sdeg_h[i] = d_deg_h[i];
            soff_m[i] = d_off_m[i]; sdeg_m[i] = d_deg_m[i];
        }
        for (int i = tid; i < 512;  i += 256) ssrc_h[i] = d_src_h[i];
        for (int i = tid; i < 1024; i += 256) ssrc_m[i] = d_src_m[i];

        const int t_g = ci * TCB + (sub >> 1);
        const int b0  = (sub & 1) * 16;

        for (int gi = 0; gi < 16; gi++) {
            const int b = b0 + gi;
            const int g = b * TT + t_g;
            const float* xh = xh_all + (size_t)g * NH * FH;
            const float* xm = xm_all + (size_t)g * NM * FM;

            __syncthreads();
            for (int i = tid; i < NH * FH / 4; i += 256)
                *(float4*)&sxh[i * 4] = *(const float4*)&xh[i * 4];
            for (int i = tid; i < NM * FM / 4; i += 256)
                *(float4*)&sxm[i * 4] = *(const float4*)&xm[i * 4];
            __syncthreads();

            for (int idx = tid; idx < NH * FH; idx += 256) {
                int n = idx >> 3, k = idx & 7;
                int o = soff_h[n], d = sdeg_h[n];
                float s = 0.f;
                for (int e = 0; e < d; e++) s += sxh[ssrc_h[o + e] * FH + k];
                sah[idx] = s;
            }
            for (int idx = tid; idx < NH * FM; idx += 256) {
                int n = idx >> 4, k = idx & 15;
                int o = soff_m[n], d = sdeg_m[n];
                float s = 0.f;
                for (int e = 0; e < d; e++) s += sxm[ssrc_m[o + e] * FM + k];
                sam[idx] = s;
            }
            __syncthreads();

            // packed output: unit pairs {2jp, 2jp+1}
            for (int idx = tid; idx < NH * HG / 2; idx += 256) {
                int n = idx >> 5, jp = idx & 31;
                int j0 = 2 * jp;
                u64 acc = *(const u64*)&sb[j0];
                #pragma unroll
                for (int k = 0; k < FH; k++) {
                    u64 a1, a2;
                    PACK2(a1, sah[n * FH + k]);
                    FMA2(acc, a1, *(const u64*)&swh[k * HG + j0]);
                    PACK2(a2, sxh[n * FH + k]);
                    FMA2(acc, a2, *(const u64*)&swr[k * HG + j0]);
                }
                #pragma unroll
                for (int k = 0; k < FM; k++) {
                    u64 am;
                    PACK2(am, sam[n * FM + k]);
                    FMA2(acc, am, *(const u64*)&swm[k * HG + j0]);
                }
                float lo, hi;
                UNPACK2(lo, hi, acc);
                float2 v;
                v.x = lo > 0.f ? lo : 0.01f * lo;
                v.y = hi > 0.f ? hi : 0.01f * hi;
                *(float2*)&g_x[(((size_t)n * TT + t_g) * BB + b) * HG + j0] = v;
            }
        }
        __syncthreads();
        if (tid == 0) {
            __threadfence();
            atomicAdd(&d_cnt[ci], 1);
        }
        return;
    }

    if (role == 1) {
        // ============ xgemm producer: FFMA2 + duplicated-x staging ==========
        const int n  = sub;
        const int t0 = ci * TCB;

        float* sW = sm + XG_SW;
        float* sb = sm + XG_SB;
        float* xd = sm + XG_SX;   // [k][2b] stride 66

        const float* w = W_ih + (size_t)n * 256 * 64;
        for (int i = tid; i < 16384; i += 256) {
            int j = i >> 6, k = i & 63;
            sW[k * 256 + j] = w[i];
        }
        sb[tid] = b_ih[n * 256 + tid] + b_hh[n * 256 + tid];

        const int tm = tid >> 5;
        const int tn = tid & 31;
        const int sb_b = tid >> 3;
        const int sb_k = (tid & 7) << 3;
        __syncthreads();

        u64 binit[4];
        #pragma unroll
        for (int gg = 0; gg < 4; gg++)
            binit[gg] = *(const u64*)&sb[gg * 64 + 2 * tn];

        wait_cnt(&d_cnt[ci], GPC);

        const float* xbase = g_x + ((size_t)n * TT + t0) * BB * HG;
        float* gbase = g_gates + ((size_t)n * TT + t0) * BB * 256;

        for (int tt = 0; tt < TCB; tt++) {
            const float* xt = xbase + (size_t)tt * BB * HG;
            float4 v0 = *(const float4*)&xt[sb_b * HG + sb_k];
            float4 v1 = *(const float4*)&xt[sb_b * HG + sb_k + 4];
            *(float2*)&xd[(sb_k + 0) * 66 + 2 * sb_b] = make_float2(v0.x, v0.x);
            *(float2*)&xd[(sb_k + 1) * 66 + 2 * sb_b] = make_float2(v0.y, v0.y);
            *(float2*)&xd[(sb_k + 2) * 66 + 2 * sb_b] = make_float2(v0.z, v0.z);
            *(float2*)&xd[(sb_k + 3) * 66 + 2 * sb_b] = make_float2(v0.w, v0.w);
            *(float2*)&xd[(sb_k + 4) * 66 + 2 * sb_b] = make_float2(v1.x, v1.x);
            *(float2*)&xd[(sb_k + 5) * 66 + 2 * sb_b] = make_float2(v1.y, v1.y);
            *(float2*)&xd[(sb_k + 6) * 66 + 2 * sb_b] = make_float2(v1.z, v1.z);
            *(float2*)&xd[(sb_k + 7) * 66 + 2 * sb_b] = make_float2(v1.w, v1.w);
            __syncthreads();

            u64 acc[16];
            #pragma unroll
            for (int mi = 0; mi < 4; mi++)
                #pragma unroll
                for (int gg = 0; gg < 4; gg++) acc[mi * 4 + gg] = binit[gg];

            #pragma unroll 4
            for (int k = 0; k < 64; k++) {
                u64 xx[4];
                #pragma unroll
                for (int mi = 0; mi < 4; mi++)
                    xx[mi] = *(const u64*)&xd[k * 66 + 8 * tm + 2 * mi];
                #pragma unroll
                for (int gg = 0; gg < 4; gg++) {
                    u64 wv = *(const u64*)&sW[k * 256 + gg * 64 + 2 * tn];
                    #pragma unroll
                    for (int mi = 0; mi < 4; mi++)
                        FMA2(acc[mi * 4 + gg], xx[mi], wv);
                }
            }

            float* gt = gbase + (size_t)tt * BB * 256;
            #pragma unroll
            for (int mi = 0; mi < 4; mi++)
                #pragma unroll
                for (int gg = 0; gg < 4; gg++)
                    *(u64*)&gt[(4 * tm + mi) * 256 + gg * 64 + 2 * tn] =
                        acc[mi * 4 + gg];
            __syncthreads();

            if ((tt & (TF - 1)) == TF - 1 && tid == 0) {
                __threadfence();
                atomicExch(&d_flag[n * NCK + (t0 + tt) / TF], 1);
            }
        }
        return;
    }

    // ============ consumer role: LSTM, FFMA2 + LDS.128 weight reads =========
    const int n  = sub;
    const int tm = tid >> 5;   // warp = batch group 4tm..4tm+3
    const int tn = tid & 31;   // lane = unit pair {2tn, 2tn+1}

    float* sWhh  = sm + O_WHH;   // repacked [k][tn][8]
    float* shl   = sm + O_HL;
    float* sWlin = sm + O_WL;
    float* sblin = sm + O_BL;

    // repack: j = gg*64 + 2*tn2 + du  ->  k*256 + (gg>>1)*128 + tn2*4 + (gg&1)*2 + du
    const float* whh = W_hh + (size_t)n * 256 * 64;
    for (int i = tid; i < 16384; i += 256) {
        int j = i >> 6, k = i & 63;
        int gg = j >> 6, r = j & 63, tn2 = r >> 1, du = r & 1;
        sWhh[k * 256 + (gg >> 1) * 128 + tn2 * 4 + (gg & 1) * 2 + du] = whh[i];
    }
    for (int i = tid; i < FUT * HL; i += 256) sWlin[i] = W_lin[i];
    if (tid < FUT) sblin[tid] = b_lin[tid];
    __syncthreads();

    const int* flg = &d_flag[n * NCK];

    float h0[4], h1[4], c[4][2];
    #pragma unroll
    for (int mi = 0; mi < 4; mi++) {
        h0[mi] = 0.f; h1[mi] = 0.f;
        c[mi][0] = 0.f; c[mi][1] = 0.f;
    }

    const float* gptr = g_gates + (size_t)n * TT * BB * 256;

    wait_flag(&flg[0]);
    u64 gb[4][4];
    #pragma unroll
    for (int mi = 0; mi < 4; mi++)
        #pragma unroll
        for (int gg = 0; gg < 4; gg++)
            gb[mi][gg] = *(const u64*)&gptr[(4 * tm + mi) * 256 + gg * 64 + 2 * tn];

    for (int t = 0; t < TT; t++) {
        u64 acc[4][4];
        #pragma unroll
        for (int mi = 0; mi < 4; mi++)
            #pragma unroll
            for (int gg = 0; gg < 4; gg++) acc[mi][gg] = gb[mi][gg];

        if (t + 1 < TT) {
            if (((t + 1) & (TF - 1)) == 0)
                wait_flag(&flg[(t + 1) >> 4]);
            const float* gnx = gptr + (size_t)(t + 1) * BB * 256;
            #pragma unroll
            for (int mi = 0; mi < 4; mi++)
                #pragma unroll
                for (int gg = 0; gg < 4; gg++)
                    gb[mi][gg] = *(const u64*)&gnx[(4 * tm + mi) * 256 + gg * 64 + 2 * tn];
        }

        // packed GEMM: h via shfl; weights as 2 x LDS.128 per k
        #pragma unroll 8
        for (int k = 0; k < 64; k++) {
            const int r = k >> 1;
            u64 hx[4];
            #pragma unroll
            for (int mi = 0; mi < 4; mi++) {
                float hv = __shfl_sync(0xffffffffu,
                                       (k & 1) ? h1[mi] : h0[mi], r);
                PACK2(hx[mi], hv);
            }
            float4 wA = *(const float4*)&sWhh[k * 256 + tn * 4];
            float4 wB = *(const float4*)&sWhh[k * 256 + 128 + tn * 4];
            u64 w0 = *(const u64*)&wA.x;
            u64 w1 = *(const u64*)&wA.z;
            u64 w2 = *(const u64*)&wB.x;
            u64 w3 = *(const u64*)&wB.z;
            #pragma unroll
            for (int mi = 0; mi < 4; mi++) {
                FMA2(acc[mi][0], hx[mi], w0);
                FMA2(acc[mi][1], hx[mi], w1);
                FMA2(acc[mi][2], hx[mi], w2);
                FMA2(acc[mi][3], hx[mi], w3);
            }
        }

        // cell update (gate order i, f, g, o)
        #pragma unroll
        for (int mi = 0; mi < 4; mi++) {
            float iv[2], fv[2], gv[2], ov[2];
            UNPACK2(iv[0], iv[1], acc[mi][0]);
            UNPACK2(fv[0], fv[1], acc[mi][1]);
            UNPACK2(gv[0], gv[1], acc[mi][2]);
            UNPACK2(ov[0], ov[1], acc[mi][3]);
            {
                float ig = sigm(iv[0]);
                float fg = sigm(fv[0]);
                float gv0 = tanh_fast(gv[0]);
                float og = sigm(ov[0]);
                float cc = fg * c[mi][0] + ig * gv0;
                c[mi][0] = cc;
                h0[mi] = og * tanh_fast(cc);
            }
            {
                float ig = sigm(iv[1]);
                float fg = sigm(fv[1]);
                float gv1 = tanh_fast(gv[1]);
                float og = sigm(ov[1]);
                float cc = fg * c[mi][1] + ig * gv1;
                c[mi][1] = cc;
                h1[mi] = og * tanh_fast(cc);
            }
        }
    }

    #pragma unroll
    for (int mi = 0; mi < 4; mi++) {
        shl[(2 * tn + 0) * 33 + (4 * tm + mi)] = h0[mi];
        shl[(2 * tn + 1) * 33 + (4 * tm + mi)] = h1[mi];
    }
    __syncthreads();

    for (int idx = tid; idx < BB * FUT; idx += 256) {
        int b = idx / FUT;
        int f = idx % FUT;
        float acc = sblin[f];
        #pragma unroll
        for (int u = 0; u < HL; u++)
            acc += shl[u * 33 + b] * sWlin[f * HL + u];
        float v = acc > 0.f ? acc : 0.01f * acc;
        out[((size_t)b * NH + n) * FUT + f] = v;
    }
}

// ---------------------------------------------------------------------------
extern "C" void kernel_launch(void* const* d_in, const int* in_sizes, int n_in,
                              void* d_out, int out_size)
{
    const float* data_meteo = (const float*)d_in[0];
    const float* data_hydro = (const float*)d_in[1];
    const int*   eh         = (const int*)  d_in[2];
    const int*   em         = (const int*)  d_in[3];
    const float* W_rel_m    = (const float*)d_in[4];
    const float* b_rel_m    = (const float*)d_in[5];
    const float* W_root_m   = (const float*)d_in[6];
    const float* W_rel_h    = (const float*)d_in[7];
    const float* b_rel_h    = (const float*)d_in[8];
    const float* W_root_h   = (const float*)d_in[9];
    const float* W_ih       = (const float*)d_in[10];
    const float* W_hh       = (const float*)d_in[11];
    const float* b_ih       = (const float*)d_in[12];
    const float* b_hh       = (const float*)d_in[13];
    const float* W_lin      = (const float*)d_in[14];
    const float* b_lin      = (const float*)d_in[15];

    const int Eh = in_sizes[2] / 2;
    const int Em = in_sizes[3] / 2;

    csr_kernel<<<1, 256>>>(eh, em, Eh, Em);

    cudaFuncSetAttribute(fused_kernel,
                         cudaFuncAttributeMaxDynamicSharedMemorySize,
                         FUSED_BYTES);
    const int grid = GPC + 2 * NH + (NPB - 1) * GRP;   // 1472
    fused_kernel<<<grid, 256, FUSED_BYTES>>>(
        data_meteo, data_hydro,
        W_rel_m, b_rel_m, W_root_m,
        W_rel_h, b_rel_h, W_root_h,
        W_ih, W_hh, b_ih, b_hh, W_lin, b_lin, (float*)d_out);
}